// round 10
// baseline (speedup 1.0000x reference)
#include <cuda_runtime.h>
#include <math.h>

#define BATCH   2
#define SEQ     2048
#define DMODEL  2048
#define NHEADS  16
#define DHEAD   128
#define SCALE   0.08838834764831845f   // 1/sqrt(128)

// Scratch (allocation-free: __device__ globals)
__device__ float g_Q[BATCH*NHEADS*SEQ*DHEAD];   // [B][H][S][Dh] tf32-rounded, Q pre-scaled
__device__ float g_K[BATCH*NHEADS*SEQ*DHEAD];
__device__ float g_V[BATCH*NHEADS*SEQ*DHEAD];
// Fragment-permuted operands (tf32-rounded):
__device__ float g_Xp [BATCH*SEQ*DMODEL];       // A-frag: [m-tile(32)][slab(64)][4096]
__device__ float g_Zp [BATCH*SEQ*NHEADS*DHEAD]; // A-frag
__device__ float g_Wqp[NHEADS*DMODEL*DHEAD];    // B-frag (pre-scaled by 1/sqrt(128))
__device__ float g_Wkp[NHEADS*DMODEL*DHEAD];
__device__ float g_Wvp[NHEADS*DMODEL*DHEAD];
__device__ float g_WOp[NHEADS*DHEAD*DMODEL];

#define SLAB_WORDS 4096
#define MAT_WORDS  (64*SLAB_WORDS)

// ---------------------------------------------------------------------------
// helpers
// ---------------------------------------------------------------------------
__device__ __forceinline__ unsigned f2tf32(float x) {
    unsigned y;
    asm("cvt.rna.tf32.f32 %0, %1;" : "=r"(y) : "f"(x));
    return y;
}
__device__ __forceinline__ float f2tf32f(float x) { return __uint_as_float(f2tf32(x)); }

__device__ __forceinline__ void mma_tf32(float* c, const unsigned* a, const unsigned* b) {
    asm volatile(
        "mma.sync.aligned.m16n8k8.row.col.f32.tf32.tf32.f32 "
        "{%0,%1,%2,%3}, {%4,%5,%6,%7}, {%8,%9}, {%0,%1,%2,%3};\n"
        : "+f"(c[0]), "+f"(c[1]), "+f"(c[2]), "+f"(c[3])
        : "r"(a[0]), "r"(a[1]), "r"(a[2]), "r"(a[3]), "r"(b[0]), "r"(b[1]));
}

__device__ __forceinline__ void cp_async16(void* smem_dst, const void* gsrc) {
    unsigned saddr = (unsigned)__cvta_generic_to_shared(smem_dst);
    asm volatile("cp.async.ca.shared.global [%0], [%1], 16;\n" :: "r"(saddr), "l"(gsrc));
}
#define CP_COMMIT() asm volatile("cp.async.commit_group;\n" ::: "memory")
#define CP_WAIT0()  asm volatile("cp.async.wait_group 0;\n" ::: "memory")
#define CP_WAIT1()  asm volatile("cp.async.wait_group 1;\n" ::: "memory")
#define CP_WAIT2()  asm volatile("cp.async.wait_group 2;\n" ::: "memory")

// A-frag word index within a 128x32 slab
__device__ __forceinline__ int afrag(int m, int k) {
    return ((((m >> 4) * 4 + (k >> 3)) * 32 + (m & 7) * 4 + (k & 3)) << 2)
           + (((k & 4) >> 1) | ((m & 8) >> 3));
}

// ---------------------------------------------------------------------------
// Prepass: permute+round A operand (X -> g_Xp)
// ---------------------------------------------------------------------------
__global__ __launch_bounds__(256) void permute_A_kernel(
    const float* __restrict__ src, float* __restrict__ dst, int nchunks)
{
    int gid = blockIdx.x * blockDim.x + threadIdx.x;
    if (gid >= nchunks) return;
    int c    = gid & 1023;
    int slab = (gid >> 10) & 63;
    int mt_g = gid >> 16;
    int lane = c & 31, t = c >> 5;
    int kt = t & 3, mt = t >> 2;
    int m = mt_g * 128 + mt * 16 + (lane >> 2);
    int k = slab * 32 + kt * 8 + (lane & 3);
    const float* s = src + (size_t)m * DMODEL + k;
    float4 o;
    o.x = f2tf32f(s[0]);
    o.y = f2tf32f(s[(size_t)8 * DMODEL]);
    o.z = f2tf32f(s[4]);
    o.w = f2tf32f(s[(size_t)8 * DMODEL + 4]);
    *(float4*)(dst + (size_t)gid * 4) = o;
}

// ---------------------------------------------------------------------------
// Prepass: permute+round B operand (optionally scaled pre-rounding).
// ---------------------------------------------------------------------------
__global__ __launch_bounds__(256) void permute_B_kernel(
    const float* __restrict__ src, float* __restrict__ dst,
    size_t mat_off_stride, int ld, int nchunks, float scl)
{
    int gid = blockIdx.x * blockDim.x + threadIdx.x;
    if (gid >= nchunks) return;
    int c    = gid & 1023;
    int slab = (gid >> 10) & 63;
    int mat  = gid >> 16;
    int pair = c * 2;
    int lane = pair & 31, t = pair >> 5;
    int nt8 = t & 15, kt = t >> 4;
    int k = slab * 32 + kt * 8 + (lane & 3);
    int n = nt8 * 8 + (lane >> 2);
    const float* s = src + mat * mat_off_stride + (size_t)k * ld + n;
    float4 o;
    o.x = f2tf32f(s[0] * scl);
    o.y = f2tf32f(s[(size_t)4 * ld] * scl);
    o.z = f2tf32f(s[(size_t)1 * ld] * scl);
    o.w = f2tf32f(s[(size_t)5 * ld] * scl);
    *(float4*)(dst + (size_t)gid * 4) = o;
}

// ---------------------------------------------------------------------------
// GEMM mainloop: block tile 128x128, k-slab 32, 3-stage cp.async.
// ---------------------------------------------------------------------------
#define GSTAGE_WORDS (2 * SLAB_WORDS)            // 8192
#define GEMM_SMEM_BYTES (3 * GSTAGE_WORDS * 4)   // 98304

__device__ __forceinline__ void gemm_issue_p(
    float* stage, const float* __restrict__ Ablk, const float* __restrict__ Bblk, int tid)
{
    #pragma unroll
    for (int i = 0; i < 4; i++) {
        int c = tid + i * 256;
        cp_async16(stage + c * 4, Ablk + (size_t)c * 4);
        cp_async16(stage + SLAB_WORDS + c * 4, Bblk + (size_t)c * 4);
    }
}

__device__ __forceinline__ void gemm_compute_p(
    const float* stage, float c[4][4][4], int warpM, int warpN, int lane)
{
    const uint4* A4 = (const uint4*)stage;
    const uint2* B2 = (const uint2*)(stage + SLAB_WORDS);
    #pragma unroll
    for (int kt = 0; kt < 4; kt++) {
        uint4 a[4]; uint2 b[4];
        #pragma unroll
        for (int mi = 0; mi < 4; mi++)
            a[mi] = A4[((warpM * 4 + mi) * 4 + kt) * 32 + lane];
        #pragma unroll
        for (int ni = 0; ni < 4; ni++)
            b[ni] = B2[(kt * 16 + warpN * 4 + ni) * 32 + lane];
        #pragma unroll
        for (int mi = 0; mi < 4; mi++)
            #pragma unroll
            for (int ni = 0; ni < 4; ni++)
                mma_tf32(c[mi][ni], (const unsigned*)&a[mi], (const unsigned*)&b[ni]);
    }
}

// ---------------------------------------------------------------------------
// Phase 1: QKV projection. grid = (16 heads, 32 m-tiles, 3 {Q,K,V})
// ---------------------------------------------------------------------------
__global__ __launch_bounds__(256) void qkv_gemm_tc(
    const float* __restrict__ bq, const float* __restrict__ bk, const float* __restrict__ bv)
{
    extern __shared__ __align__(16) float smp[];

    const float* W; const float* bias; float* out; float bscale;
    if (blockIdx.z == 0)      { W = g_Wqp; bias = bq; out = g_Q; bscale = SCALE; }
    else if (blockIdx.z == 1) { W = g_Wkp; bias = bk; out = g_K; bscale = 1.f; }
    else                      { W = g_Wvp; bias = bv; out = g_V; bscale = 1.f; }

    const int h   = blockIdx.x;
    const int m0  = blockIdx.y * 128;
    const int tid = threadIdx.x;
    const int warp = tid >> 5, lane = tid & 31;
    const int warpM = warp >> 2, warpN = warp & 3;
    const int lq = lane >> 2, lr = lane & 3;
    const float* Ablk0 = g_Xp + (size_t)(m0 >> 7) * MAT_WORDS;
    const float* Bblk0 = W + (size_t)h * MAT_WORDS;

    float c[4][4][4];
    #pragma unroll
    for (int mi = 0; mi < 4; mi++)
        #pragma unroll
        for (int ni = 0; ni < 4; ni++)
            #pragma unroll
            for (int j = 0; j < 4; j++) c[mi][ni][j] = 0.f;

    gemm_issue_p(smp,                    Ablk0,                  Bblk0,                  tid); CP_COMMIT();
    gemm_issue_p(smp + GSTAGE_WORDS,     Ablk0 + SLAB_WORDS,     Bblk0 + SLAB_WORDS,     tid); CP_COMMIT();
    gemm_issue_p(smp + 2*GSTAGE_WORDS,   Ablk0 + 2*SLAB_WORDS,   Bblk0 + 2*SLAB_WORDS,   tid); CP_COMMIT();

    int st = 0;
    for (int s = 0; s < 64; s++) {
        float* cur = smp + st * GSTAGE_WORDS;
        CP_WAIT2();
        __syncthreads();
        gemm_compute_p(cur, c, warpM, warpN, lane);
        __syncthreads();
        if (s + 3 < 64)
            gemm_issue_p(cur, Ablk0 + (size_t)(s + 3) * SLAB_WORDS,
                              Bblk0 + (size_t)(s + 3) * SLAB_WORDS, tid);
        CP_COMMIT();
        st = (st == 2) ? 0 : st + 1;
    }

    #pragma unroll
    for (int mi = 0; mi < 4; mi++) {
        #pragma unroll
        for (int half = 0; half < 2; half++) {
            int m = m0 + warpM * 64 + mi * 16 + lq + half * 8;
            int b_ = m >> 11, sdx = m & 2047;
            float* orow = out + (((size_t)(b_ * NHEADS + h)) * SEQ + sdx) * DHEAD;
            #pragma unroll
            for (int ni = 0; ni < 4; ni++) {
                int n = warpN * 32 + ni * 8 + 2 * lr;
                float2 r;
                r.x = f2tf32f(c[mi][ni][half * 2 + 0] + bias[h * DHEAD + n]     * bscale);
                r.y = f2tf32f(c[mi][ni][half * 2 + 1] + bias[h * DHEAD + n + 1] * bscale);
                *(float2*)(orow + n) = r;
            }
        }
    }
}

// ---------------------------------------------------------------------------
// Phase 2: causal flash attention, q-tile 128, kv-tile 64, 512 threads,
// separate K/V buffers with one-tile-ahead prefetch (no exposed load latency).
// grid = (8 pair-slots, B*H); CTA runs q-tiles {15-i, i} (34 kv-tiles total).
// Commit-group invariant at loop top: pending = [K(kt), V(kt)] -> wait_group 1.
// ---------------------------------------------------------------------------
#define AQ  0
#define AK  (128*132)            // 16896
#define AV  (AK + 64*132)        // 25344
#define AP  (AV + 64*132)        // 33792
#define AMX (AP + 128*68)        // 42496
#define ASM (AMX + 256)          // 42752
#define ATT_SMEM_BYTES ((ASM + 256) * 4)   // 172032

__global__ __launch_bounds__(512, 1) void attn_tc()
{
    extern __shared__ __align__(16) unsigned smu[];
    unsigned* Qs = smu + AQ;     // [128][132]
    unsigned* Ks = smu + AK;     // [64][132]
    unsigned* Vs = smu + AV;     // [64][132]
    unsigned* Ps = smu + AP;     // [128][68]
    float* smax = (float*)(smu + AMX);   // [2][128]
    float* ssum = (float*)(smu + ASM);   // [2][128]

    const int tid = threadIdx.x;
    const int warp = tid >> 5, lane = tid & 31;
    const int warpR = warp >> 1, warpC = warp & 1;
    const int lq = lane >> 2, lr = lane & 3;
    const int bh = blockIdx.y;
    const int b  = bh >> 4, h = bh & 15;
    const int r_loc = warpR * 16 + lq;     // 0..127

    const float* Qg = g_Q + (size_t)(b * NHEADS + h) * SEQ * DHEAD;
    const float* Kg = g_K + (size_t)(b * NHEADS + h) * SEQ * DHEAD;
    const float* Vg = g_V + (size_t)(b * NHEADS + h) * SEQ * DHEAD;

    const int srow = tid >> 5, scc = (tid & 31) * 4;   // staging: 16 rows per iter

    for (int run = 0; run < 2; run++) {
        const int qt = (run == 0) ? (15 - (int)blockIdx.x) : (int)blockIdx.x;
        const int q0 = qt * 128;
        const int ntiles = 2 * qt + 2;

        // stage Q (128x128); then K(0); then V(0) — three commit groups
        #pragma unroll
        for (int i = 0; i < 8; i++) {
            int row = srow + i * 16;
            cp_async16(Qs + row * 132 + scc, Qg + (size_t)(q0 + row) * DHEAD + scc);
        }
        CP_COMMIT();
        #pragma unroll
        for (int i = 0; i < 4; i++) {
            int row = srow + i * 16;
            cp_async16(Ks + row * 132 + scc, Kg + (size_t)row * DHEAD + scc);
        }
        CP_COMMIT();
        #pragma unroll
        for (int i = 0; i < 4; i++) {
            int row = srow + i * 16;
            cp_async16(Vs + row * 132 + scc, Vg + (size_t)row * DHEAD + scc);
        }
        CP_COMMIT();

        float o[8][4];
        #pragma unroll
        for (int ni = 0; ni < 8; ni++)
            #pragma unroll
            for (int j = 0; j < 4; j++) o[ni][j] = 0.f;
        float m0v = -INFINITY, m1v = -INFINITY, l0 = 0.f, l1 = 0.f;

        for (int kt = 0; kt < ntiles; kt++) {
            const int k0t = kt * 64;
            CP_WAIT1();        // K(kt) (and Q on kt==0) arrived; V(kt) may be in flight
            __syncthreads();

            // S = Q K^T : warp 16x32, k=128
            float s[4][4];
            #pragma unroll
            for (int ni = 0; ni < 4; ni++)
                #pragma unroll
                for (int j = 0; j < 4; j++) s[ni][j] = 0.f;

            #pragma unroll
            for (int kk = 0; kk < 128; kk += 8) {
                unsigned aq[4], bb[2];
                const int kc = kk + lr;
                aq[0] = Qs[r_loc * 132 + kc];       aq[1] = Qs[(r_loc + 8) * 132 + kc];
                aq[2] = Qs[r_loc * 132 + kc + 4];   aq[3] = Qs[(r_loc + 8) * 132 + kc + 4];
                #pragma unroll
                for (int ni = 0; ni < 4; ni++) {
                    int nb = warpC * 32 + ni * 8 + lq;
                    bb[0] = Ks[nb * 132 + kc];
                    bb[1] = Ks[nb * 132 + kc + 4];
                    mma_tf32(s[ni], aq, bb);
                }
            }

            // causal mask + per-warp row max
            const int r0g = q0 + r_loc, r1g = r0g + 8;
            float mx0 = -1e30f, mx1 = -1e30f;
            #pragma unroll
            for (int ni = 0; ni < 4; ni++) {
                int cb = k0t + warpC * 32 + ni * 8 + 2 * lr;
                if (cb     > r0g) s[ni][0] = -1e30f;
                if (cb + 1 > r0g) s[ni][1] = -1e30f;
                if (cb     > r1g) s[ni][2] = -1e30f;
                if (cb + 1 > r1g) s[ni][3] = -1e30f;
                mx0 = fmaxf(mx0, fmaxf(s[ni][0], s[ni][1]));
                mx1 = fmaxf(mx1, fmaxf(s[ni][2], s[ni][3]));
            }
            mx0 = fmaxf(mx0, __shfl_xor_sync(0xffffffffu, mx0, 1));
            mx0 = fmaxf(mx0, __shfl_xor_sync(0xffffffffu, mx0, 2));
            mx1 = fmaxf(mx1, __shfl_xor_sync(0xffffffffu, mx1, 1));
            mx1 = fmaxf(mx1, __shfl_xor_sync(0xffffffffu, mx1, 2));
            if (lr == 0) {
                smax[warpC * 128 + r_loc]     = mx0;
                smax[warpC * 128 + r_loc + 8] = mx1;
            }
            __syncthreads();   // smax visible; ALL warps done reading Ks

            // prefetch K(kt+1) into Ks — lands during softmax + PV of this tile
            if (kt + 1 < ntiles) {
                #pragma unroll
                for (int i = 0; i < 4; i++) {
                    int row = srow + i * 16;
                    cp_async16(Ks + row * 132 + scc,
                               Kg + (size_t)(k0t + 64 + row) * DHEAD + scc);
                }
            }
            CP_COMMIT();   // unconditional: keeps group accounting fixed

            mx0 = fmaxf(mx0, smax[(warpC ^ 1) * 128 + r_loc]);
            mx1 = fmaxf(mx1, smax[(warpC ^ 1) * 128 + r_loc + 8]);

            float mn0 = fmaxf(m0v, mx0), mn1 = fmaxf(m1v, mx1);
            float ef0 = __expf(m0v - mn0), ef1 = __expf(m1v - mn1);
            m0v = mn0; m1v = mn1;

            float sum0 = 0.f, sum1 = 0.f;
            #pragma unroll
            for (int ni = 0; ni < 4; ni++) {
                float p0 = __expf(s[ni][0] - mn0);
                float p1 = __expf(s[ni][1] - mn0);
                float p2 = __expf(s[ni][2] - mn1);
                float p3 = __expf(s[ni][3] - mn1);
                sum0 += p0 + p1; sum1 += p2 + p3;
                int kc2 = warpC * 32 + ni * 8 + 2 * lr;
                Ps[r_loc * 68 + kc2]           = f2tf32(p0);
                Ps[r_loc * 68 + kc2 + 1]       = f2tf32(p1);
                Ps[(r_loc + 8) * 68 + kc2]     = f2tf32(p2);
                Ps[(r_loc + 8) * 68 + kc2 + 1] = f2tf32(p3);
            }
            sum0 += __shfl_xor_sync(0xffffffffu, sum0, 1);
            sum0 += __shfl_xor_sync(0xffffffffu, sum0, 2);
            sum1 += __shfl_xor_sync(0xffffffffu, sum1, 1);
            sum1 += __shfl_xor_sync(0xffffffffu, sum1, 2);
            if (lr == 0) {
                ssum[warpC * 128 + r_loc]     = sum0;
                ssum[warpC * 128 + r_loc + 8] = sum1;
            }
            #pragma unroll
            for (int ni = 0; ni < 8; ni++) {
                o[ni][0] *= ef0; o[ni][1] *= ef0;
                o[ni][2] *= ef1; o[ni][3] *= ef1;
            }

            CP_WAIT1();        // V(kt) arrived (K(kt+1) still in flight)
            __syncthreads();   // V + Ps + ssum visible

            l0 = l0 * ef0 + sum0 + ssum[(warpC ^ 1) * 128 + r_loc];
            l1 = l1 * ef1 + sum1 + ssum[(warpC ^ 1) * 128 + r_loc + 8];

            // O += P @ V : warp 16x64, k=64
            #pragma unroll
            for (int kk = 0; kk < 64; kk += 8) {
                unsigned ap[4], bb[2];
                const int kc = kk + lr;
                ap[0] = Ps[r_loc * 68 + kc];       ap[1] = Ps[(r_loc + 8) * 68 + kc];
                ap[2] = Ps[r_loc * 68 + kc + 4];   ap[3] = Ps[(r_loc + 8) * 68 + kc + 4];
                #pragma unroll
                for (int ni = 0; ni < 8; ni++) {
                    int nb = warpC * 64 + ni * 8 + lq;
                    bb[0] = Vs[kc * 132 + nb];
                    bb[1] = Vs[(kc + 4) * 132 + nb];
                    mma_tf32(o[ni], ap, bb);
                }
            }
            __syncthreads();   // ALL warps done reading Vs (and Ps)

            // prefetch V(kt+1) into Vs — lands during next tile's S-gemm
            if (kt + 1 < ntiles) {
                #pragma unroll
                for (int i = 0; i < 4; i++) {
                    int row = srow + i * 16;
                    cp_async16(Vs + row * 132 + scc,
                               Vg + (size_t)(k0t + 64 + row) * DHEAD + scc);
                }
            }
            CP_COMMIT();
            // pending now: [K(kt+1), V(kt+1)] — invariant restored
        }

        // normalize + scatter-write Z into A-frag permuted layout (tf32-rounded)
        float inv0 = 1.f / l0, inv1 = 1.f / l1;
        const int mglob0 = b * SEQ + q0;          // 128-aligned
        float* Zt = g_Zp + (size_t)(mglob0 >> 7) * MAT_WORDS;
        const int mrow = r_loc;                    // row within 128-row m-tile
        #pragma unroll
        for (int ni = 0; ni < 8; ni++) {
            int e = warpC * 64 + ni * 8 + 2 * lr;
            int kg = h * DHEAD + e;
            float* Zs = Zt + (size_t)(kg >> 5) * SLAB_WORDS;
            int kk = kg & 31;
            Zs[afrag(mrow,     kk)]     = f2tf32f(o[ni][0] * inv0);
            Zs[afrag(mrow,     kk + 1)] = f2tf32f(o[ni][1] * inv0);
            Zs[afrag(mrow + 8, kk)]     = f2tf32f(o[ni][2] * inv1);
            Zs[afrag(mrow + 8, kk + 1)] = f2tf32f(o[ni][3] * inv1);
        }
    }
}

// ---------------------------------------------------------------------------
// Phase 3: output projection. grid = (16 n-tiles, 32 m-tiles)
// ---------------------------------------------------------------------------
__global__ __launch_bounds__(256) void out_gemm_tc(
    const float* __restrict__ bO, float* __restrict__ out)
{
    extern __shared__ __align__(16) float smp[];

    const int n0  = blockIdx.x * 128;
    const int m0  = blockIdx.y * 128;
    const int tid = threadIdx.x;
    const int warp = tid >> 5, lane = tid & 31;
    const int warpM = warp >> 2, warpN = warp & 3;
    const int lq = lane >> 2, lr = lane & 3;

    const float* Ablk0 = g_Zp + (size_t)(m0 >> 7) * MAT_WORDS;
    const float* Bblk0 = g_WOp + (size_t)(n0 >> 7) * MAT_WORDS;

    float c[4][4][4];
    #pragma unroll
    for (int mi = 0; mi < 4; mi++)
        #pragma unroll
        for (int ni = 0; ni < 4; ni++)
            #pragma unroll
            for (int j = 0; j < 4; j++) c[mi][ni][j] = 0.f;

    gemm_issue_p(smp,                  Ablk0,                Bblk0,                tid); CP_COMMIT();
    gemm_issue_p(smp + GSTAGE_WORDS,   Ablk0 + SLAB_WORDS,   Bblk0 + SLAB_WORDS,   tid); CP_COMMIT();
    gemm_issue_p(smp + 2*GSTAGE_WORDS, Ablk0 + 2*SLAB_WORDS, Bblk0 + 2*SLAB_WORDS, tid); CP_COMMIT();

    int st = 0;
    for (int s = 0; s < 64; s++) {
        float* cur = smp + st * GSTAGE_WORDS;
        CP_WAIT2();
        __syncthreads();
        gemm_compute_p(cur, c, warpM, warpN, lane);
        __syncthreads();
        if (s + 3 < 64)
            gemm_issue_p(cur, Ablk0 + (size_t)(s + 3) * SLAB_WORDS,
                              Bblk0 + (size_t)(s + 3) * SLAB_WORDS, tid);
        CP_COMMIT();
        st = (st == 2) ? 0 : st + 1;
    }

    #pragma unroll
    for (int mi = 0; mi < 4; mi++) {
        #pragma unroll
        for (int half = 0; half < 2; half++) {
            int m = m0 + warpM * 64 + mi * 16 + lq + half * 8;
            float* orow = out + (size_t)m * DMODEL + n0;
            #pragma unroll
            for (int ni = 0; ni < 4; ni++) {
                int n = warpN * 32 + ni * 8 + 2 * lr;
                float2 r;
                r.x = c[mi][ni][half * 2 + 0] + bO[n0 + n];
                r.y = c[mi][ni][half * 2 + 1] + bO[n0 + n + 1];
                *(float2*)(orow + n) = r;
            }
        }
    }
}

// ---------------------------------------------------------------------------
extern "C" void kernel_launch(void* const* d_in, const int* in_sizes, int n_in,
                              void* d_out, int out_size)
{
    const float* x  = (const float*)d_in[0];
    const float* Wq = (const float*)d_in[1];
    const float* Wk = (const float*)d_in[2];
    const float* Wv = (const float*)d_in[3];
    const float* Wo = (const float*)d_in[4];
    const float* bq = (const float*)d_in[5];
    const float* bk = (const float*)d_in[6];
    const float* bv = (const float*)d_in[7];
    const float* bo = (const float*)d_in[8];
    float* out = (float*)d_out;

    float *pXp, *pWqp, *pWkp, *pWvp, *pWOp;
    cudaGetSymbolAddress((void**)&pXp,  g_Xp);
    cudaGetSymbolAddress((void**)&pWqp, g_Wqp);
    cudaGetSymbolAddress((void**)&pWkp, g_Wkp);
    cudaGetSymbolAddress((void**)&pWvp, g_Wvp);
    cudaGetSymbolAddress((void**)&pWOp, g_WOp);

    const int NXC = BATCH*SEQ*DMODEL/4;
    const int NWC = NHEADS*DMODEL*DHEAD/4;
    permute_A_kernel<<<(NXC+255)/256, 256>>>(x, pXp, NXC);
    permute_B_kernel<<<(NWC+255)/256, 256>>>(Wq, pWqp, (size_t)DMODEL*DHEAD, DHEAD, NWC, SCALE);
    permute_B_kernel<<<(NWC+255)/256, 256>>>(Wk, pWkp, (size_t)DMODEL*DHEAD, DHEAD, NWC, 1.f);
    permute_B_kernel<<<(NWC+255)/256, 256>>>(Wv, pWvp, (size_t)DMODEL*DHEAD, DHEAD, NWC, 1.f);
    permute_B_kernel<<<(NWC+255)/256, 256>>>(Wo, pWOp, (size_t)128, DMODEL, NWC, 1.f);

    dim3 blk(256);

    cudaFuncSetAttribute(qkv_gemm_tc, cudaFuncAttributeMaxDynamicSharedMemorySize, GEMM_SMEM_BYTES);
    qkv_gemm_tc<<<dim3(16, 32, 3), blk, GEMM_SMEM_BYTES>>>(bq, bk, bv);

    cudaFuncSetAttribute(attn_tc, cudaFuncAttributeMaxDynamicSharedMemorySize, ATT_SMEM_BYTES);
    attn_tc<<<dim3(8, 32), 512, ATT_SMEM_BYTES>>>();

    cudaFuncSetAttribute(out_gemm_tc, cudaFuncAttributeMaxDynamicSharedMemorySize, GEMM_SMEM_BYTES);
    out_gemm_tc<<<dim3(16, 32), blk, GEMM_SMEM_BYTES>>>(bo, out);
}

// round 12
// speedup vs baseline: 1.8930x; 1.8930x over previous
#include <cuda_runtime.h>
#include <cuda_fp16.h>
#include <math.h>

#define BATCH   2
#define SEQ     2048
#define DMODEL  2048
#define NHEADS  16
#define DHEAD   128
#define SCALE   0.08838834764831845f   // 1/sqrt(128)

// ---------------------------------------------------------------------------
// Scratch (allocation-free: __device__ globals)
// ---------------------------------------------------------------------------
__device__ __half g_Q [BATCH*NHEADS*SEQ*DHEAD];   // [b][h][s][e] fp16, Q pre-scaled
__device__ __half g_K [BATCH*NHEADS*SEQ*DHEAD];   // [b][h][s][e]
__device__ __half g_Vt[BATCH*NHEADS*DHEAD*SEQ];   // [b][h][e][s]  (transposed!)

// fp16 fragment-permuted operand panels (1 word = 2 fp16 along k).
// Panel = 128 rows x 2048 k = 32 slabs; slab = 4096 words.
#define SLAB_W  4096
#define PANEL_W (32*SLAB_W)   // 131072 words
__device__ unsigned g_Xp [BATCH*SEQ*DMODEL/2];     // A-frag panels (32 m-tiles)
__device__ unsigned g_Zp [BATCH*SEQ*DMODEL/2];     // A-frag panels
__device__ unsigned g_Wqp[NHEADS*DMODEL*DHEAD/2];  // B-frag panels (16 heads), pre-scaled
__device__ unsigned g_Wkp[NHEADS*DMODEL*DHEAD/2];
__device__ unsigned g_Wvp[NHEADS*DMODEL*DHEAD/2];
__device__ unsigned g_WOp[DMODEL*DMODEL/2];        // B-frag panels (16 n-tiles)

// ---------------------------------------------------------------------------
// helpers
// ---------------------------------------------------------------------------
__device__ __forceinline__ unsigned ph2(float a, float b) {
    __half2 h = __floats2half2_rn(a, b);
    return *(unsigned*)&h;
}

__device__ __forceinline__ void mma_f16(float* c, const unsigned* a, const unsigned* b) {
    asm volatile(
        "mma.sync.aligned.m16n8k16.row.col.f32.f16.f16.f32 "
        "{%0,%1,%2,%3}, {%4,%5,%6,%7}, {%8,%9}, {%0,%1,%2,%3};\n"
        : "+f"(c[0]), "+f"(c[1]), "+f"(c[2]), "+f"(c[3])
        : "r"(a[0]), "r"(a[1]), "r"(a[2]), "r"(a[3]), "r"(b[0]), "r"(b[1]));
}

__device__ __forceinline__ void cp_async16(void* smem_dst, const void* gsrc) {
    unsigned saddr = (unsigned)__cvta_generic_to_shared(smem_dst);
    asm volatile("cp.async.ca.shared.global [%0], [%1], 16;\n" :: "r"(saddr), "l"(gsrc));
}
#define CP_COMMIT() asm volatile("cp.async.commit_group;\n" ::: "memory")
#define CP_WAIT0()  asm volatile("cp.async.wait_group 0;\n" ::: "memory")
#define CP_WAIT2()  asm volatile("cp.async.wait_group 2;\n" ::: "memory")

// A-frag word index within a 128x64 fp16 slab (k even, 0..63)
__device__ __forceinline__ int afrag16(int m, int k) {
    int reg = ((k & 8) >> 2) | ((m & 8) >> 3);
    return ((((m >> 4) * 4 + (k >> 4)) * 32 + (m & 7) * 4 + ((k & 7) >> 1)) << 2) + reg;
}

// ---------------------------------------------------------------------------
// Prepass: A operand (row-major fp32 [4096][2048]) -> fp16 A-frag panels
// ---------------------------------------------------------------------------
__global__ __launch_bounds__(256) void permute_A16(
    const float* __restrict__ src, unsigned* __restrict__ dst, int nchunks)
{
    int gid = blockIdx.x * blockDim.x + threadIdx.x;
    if (gid >= nchunks) return;
    int c = gid & 1023, slab = (gid >> 10) & 31, mt_g = gid >> 15;
    int lane = c & 31, t = c >> 5;
    int kt = t & 3, mt = t >> 2;
    int m = mt_g * 128 + mt * 16 + (lane >> 2);
    int k = slab * 64 + kt * 16 + 2 * (lane & 3);
    const float* s = src + (size_t)m * DMODEL + k;
    uint4 o;
    o.x = ph2(s[0], s[1]);
    o.y = ph2(s[(size_t)8 * DMODEL], s[(size_t)8 * DMODEL + 1]);
    o.z = ph2(s[8], s[9]);
    o.w = ph2(s[(size_t)8 * DMODEL + 8], s[(size_t)8 * DMODEL + 9]);
    *(uint4*)(dst + (size_t)gid * 4) = o;
}

// ---------------------------------------------------------------------------
// Prepass: B operand -> fp16 B-frag panels (k-pairs packed, col n).
// QKV W: src[h][k][n], mat_stride=2048*128, ld=128.  WO: src[k][n], mat_stride=128, ld=2048.
// ---------------------------------------------------------------------------
__global__ __launch_bounds__(256) void permute_B16(
    const float* __restrict__ src, unsigned* __restrict__ dst,
    size_t mat_stride, int ld, float scl, int nchunks)
{
    int gid = blockIdx.x * blockDim.x + threadIdx.x;
    if (gid >= nchunks) return;
    int c = gid & 1023, slab = (gid >> 10) & 31, mat = gid >> 15;
    int p = c * 2;
    int L = p & 31, t = p >> 5;          // L even; t in 0..63
    int nt = t & 15, kt = t >> 4;
    int n = nt * 8 + (L >> 2);
    int k = slab * 64 + kt * 16 + 2 * (L & 3);
    const float* s = src + (size_t)mat * mat_stride + n;
    uint4 o;
    o.x = ph2(s[(size_t)k * ld] * scl,        s[(size_t)(k + 1) * ld] * scl);
    o.y = ph2(s[(size_t)(k + 8) * ld] * scl,  s[(size_t)(k + 9) * ld] * scl);
    o.z = ph2(s[(size_t)(k + 2) * ld] * scl,  s[(size_t)(k + 3) * ld] * scl);
    o.w = ph2(s[(size_t)(k + 10) * ld] * scl, s[(size_t)(k + 11) * ld] * scl);
    *(uint4*)(dst + (size_t)gid * 4) = o;
}

// ---------------------------------------------------------------------------
// fp16 GEMM mainloop: block tile 128x128, k-slab 64, 3-stage cp.async.
// Stage = A slab (4096 w) + B slab (4096 w) = 32KB.
// ---------------------------------------------------------------------------
#define GSTAGE_W (2 * SLAB_W)                 // 8192 words
#define GEMM_SMEM_BYTES (3 * GSTAGE_W * 4)    // 98304

__device__ __forceinline__ void gemm_issue16(
    unsigned* stage, const unsigned* __restrict__ A, const unsigned* __restrict__ B, int tid)
{
    #pragma unroll
    for (int i = 0; i < 4; i++) {
        int c = tid + i * 256;
        cp_async16(stage + c * 4, A + (size_t)c * 4);
        cp_async16(stage + SLAB_W + c * 4, B + (size_t)c * 4);
    }
}

__device__ __forceinline__ void gemm_compute16(
    const unsigned* stage, float c[4][4][4], int warpM, int warpN, int lane)
{
    const uint4* A4 = (const uint4*)stage;
    const uint2* B2 = (const uint2*)(stage + SLAB_W);
    #pragma unroll
    for (int kt = 0; kt < 4; kt++) {
        uint4 a[4]; uint2 b[4];
        #pragma unroll
        for (int mi = 0; mi < 4; mi++)
            a[mi] = A4[((warpM * 4 + mi) * 4 + kt) * 32 + lane];
        #pragma unroll
        for (int ni = 0; ni < 4; ni++)
            b[ni] = B2[(kt * 16 + warpN * 4 + ni) * 32 + lane];
        #pragma unroll
        for (int mi = 0; mi < 4; mi++)
            #pragma unroll
            for (int ni = 0; ni < 4; ni++)
                mma_f16(c[mi][ni], (const unsigned*)&a[mi], (const unsigned*)&b[ni]);
    }
}

// ---------------------------------------------------------------------------
// Phase 1: QKV projection. grid = (16 heads, 32 m-tiles, 3 {Q,K,V}).
// Q/K written fp16 row-major; V written fp16 TRANSPOSED [b][h][e][s].
// ---------------------------------------------------------------------------
__global__ __launch_bounds__(256) void qkv_gemm16(
    const float* __restrict__ bq, const float* __restrict__ bk, const float* __restrict__ bv)
{
    extern __shared__ __align__(16) unsigned smp[];

    const unsigned* W; const float* bias; float bscale;
    if (blockIdx.z == 0)      { W = g_Wqp; bias = bq; bscale = SCALE; }
    else if (blockIdx.z == 1) { W = g_Wkp; bias = bk; bscale = 1.f; }
    else                      { W = g_Wvp; bias = bv; bscale = 1.f; }

    const int h   = blockIdx.x;
    const int m0  = blockIdx.y * 128;
    const int tid = threadIdx.x;
    const int warp = tid >> 5, lane = tid & 31;
    const int warpM = warp >> 2, warpN = warp & 3;
    const int lq = lane >> 2, lr = lane & 3;
    const unsigned* Ablk0 = g_Xp + (size_t)(m0 >> 7) * PANEL_W;
    const unsigned* Bblk0 = W + (size_t)h * PANEL_W;

    float c[4][4][4];
    #pragma unroll
    for (int mi = 0; mi < 4; mi++)
        #pragma unroll
        for (int ni = 0; ni < 4; ni++)
            #pragma unroll
            for (int j = 0; j < 4; j++) c[mi][ni][j] = 0.f;

    gemm_issue16(smp,              Ablk0,              Bblk0,              tid); CP_COMMIT();
    gemm_issue16(smp + GSTAGE_W,   Ablk0 + SLAB_W,     Bblk0 + SLAB_W,     tid); CP_COMMIT();
    gemm_issue16(smp + 2*GSTAGE_W, Ablk0 + 2*SLAB_W,   Bblk0 + 2*SLAB_W,   tid); CP_COMMIT();

    int st = 0;
    for (int s = 0; s < 32; s++) {
        unsigned* cur = smp + st * GSTAGE_W;
        CP_WAIT2();
        __syncthreads();
        gemm_compute16(cur, c, warpM, warpN, lane);
        __syncthreads();
        if (s + 3 < 32)
            gemm_issue16(cur, Ablk0 + (size_t)(s + 3) * SLAB_W,
                              Bblk0 + (size_t)(s + 3) * SLAB_W, tid);
        CP_COMMIT();
        st = (st == 2) ? 0 : st + 1;
    }

    #pragma unroll
    for (int mi = 0; mi < 4; mi++) {
        #pragma unroll
        for (int half_ = 0; half_ < 2; half_++) {
            int m = m0 + warpM * 64 + mi * 16 + lq + half_ * 8;
            int b_ = m >> 11, sdx = m & 2047;
            const size_t head = (size_t)(b_ * NHEADS + h);
            #pragma unroll
            for (int ni = 0; ni < 4; ni++) {
                int n = warpN * 32 + ni * 8 + 2 * lr;
                float v0 = c[mi][ni][half_ * 2 + 0] + bias[h * DHEAD + n]     * bscale;
                float v1 = c[mi][ni][half_ * 2 + 1] + bias[h * DHEAD + n + 1] * bscale;
                if (blockIdx.z == 2) {
                    __half* vt = g_Vt + head * DHEAD * SEQ;
                    vt[(size_t)n * SEQ + sdx]       = __float2half_rn(v0);
                    vt[(size_t)(n + 1) * SEQ + sdx] = __float2half_rn(v1);
                } else {
                    __half* orow = (blockIdx.z == 0 ? g_Q : g_K)
                                   + (head * SEQ + sdx) * DHEAD;
                    *(unsigned*)(orow + n) = ph2(v0, v1);
                }
            }
        }
    }
}

// ---------------------------------------------------------------------------
// Phase 2: causal flash attention (fp16 MMAs, R6 control flow).
// grid = (16 pair-slots, B*H); CTA runs q-tiles {31-i, i}. q-tile 64, kv 64.
// smem (words): Qs[64][68] Ks[64][68] Vs[128][36] Ps[64][36] smax[128] ssum[128]
// ---------------------------------------------------------------------------
#define AQ  0
#define AK  (64*68)            // 4352
#define AV  (AK + 64*68)       // 8704
#define AP  (AV + 128*36)      // 13312
#define AMX (AP + 64*36)       // 15616
#define ASM (AMX + 128)        // 15744
#define ATT_SMEM_BYTES ((ASM + 128) * 4)   // 63488

__global__ __launch_bounds__(256, 2) void attn16()
{
    extern __shared__ __align__(16) unsigned smu[];
    unsigned* Qs = smu + AQ;
    unsigned* Ks = smu + AK;
    unsigned* Vs = smu + AV;
    unsigned* Ps = smu + AP;
    float* smax = (float*)(smu + AMX);   // [2][64]
    float* ssum = (float*)(smu + ASM);   // [2][64]

    const int tid = threadIdx.x;
    const int warp = tid >> 5, lane = tid & 31;
    const int warpR = warp >> 1, warpC = warp & 1;
    const int lq = lane >> 2, lr = lane & 3;
    const int bh = blockIdx.y;
    const int b  = bh >> 4, h = bh & 15;
    const int r_loc = warpR * 16 + lq;

    const __half* Qg  = g_Q  + (size_t)(b * NHEADS + h) * SEQ * DHEAD;
    const __half* Kg  = g_K  + (size_t)(b * NHEADS + h) * SEQ * DHEAD;
    const __half* Vtg = g_Vt + (size_t)(b * NHEADS + h) * DHEAD * SEQ;

    for (int run = 0; run < 2; run++) {
        const int qt = (run == 0) ? (31 - (int)blockIdx.x) : (int)blockIdx.x;
        const int q0 = qt * 64;
        const int ntiles = qt + 1;

        // stage Q (64 rows x 64 words)
        #pragma unroll
        for (int i = 0; i < 4; i++) {
            int idx = tid + i * 256;
            int row = idx >> 4, cw = (idx & 15) * 4;
            cp_async16(Qs + row * 68 + cw, Qg + (size_t)(q0 + row) * DHEAD + cw * 2);
        }
        CP_COMMIT();

        float o[8][4];
        #pragma unroll
        for (int ni = 0; ni < 8; ni++)
            #pragma unroll
            for (int j = 0; j < 4; j++) o[ni][j] = 0.f;
        float m0v = -INFINITY, m1v = -INFINITY, l0 = 0.f, l1 = 0.f;

        for (int kt2 = 0; kt2 < ntiles; kt2++) {
            const int k0t = kt2 * 64;
            __syncthreads();   // Vs/Ps free (prev PV done)
            // stage K tile (64 rows x 64 words)
            #pragma unroll
            for (int i = 0; i < 4; i++) {
                int idx = tid + i * 256;
                int row = idx >> 4, cw = (idx & 15) * 4;
                cp_async16(Ks + row * 68 + cw, Kg + (size_t)(k0t + row) * DHEAD + cw * 2);
            }
            CP_COMMIT();
            CP_WAIT0();
            __syncthreads();   // K (and Q on first tile) visible

            // S = Q K^T : warp 16x32, k=128 -> 8 k16 steps
            float s[4][4];
            #pragma unroll
            for (int ni = 0; ni < 4; ni++)
                #pragma unroll
                for (int j = 0; j < 4; j++) s[ni][j] = 0.f;

            #pragma unroll
            for (int kt = 0; kt < 8; kt++) {
                unsigned aq[4], bb[2];
                const int kw = kt * 8 + lr;
                aq[0] = Qs[r_loc * 68 + kw];        aq[1] = Qs[(r_loc + 8) * 68 + kw];
                aq[2] = Qs[r_loc * 68 + kw + 4];    aq[3] = Qs[(r_loc + 8) * 68 + kw + 4];
                #pragma unroll
                for (int ni = 0; ni < 4; ni++) {
                    int nb = warpC * 32 + ni * 8 + lq;
                    bb[0] = Ks[nb * 68 + kw];
                    bb[1] = Ks[nb * 68 + kw + 4];
                    mma_f16(s[ni], aq, bb);
                }
            }

            const int r0g = q0 + r_loc, r1g = r0g + 8;
            float mx0 = -1e30f, mx1 = -1e30f;
            #pragma unroll
            for (int ni = 0; ni < 4; ni++) {
                int cb = k0t + warpC * 32 + ni * 8 + 2 * lr;
                if (cb     > r0g) s[ni][0] = -1e30f;
                if (cb + 1 > r0g) s[ni][1] = -1e30f;
                if (cb     > r1g) s[ni][2] = -1e30f;
                if (cb + 1 > r1g) s[ni][3] = -1e30f;
                mx0 = fmaxf(mx0, fmaxf(s[ni][0], s[ni][1]));
                mx1 = fmaxf(mx1, fmaxf(s[ni][2], s[ni][3]));
            }
            mx0 = fmaxf(mx0, __shfl_xor_sync(0xffffffffu, mx0, 1));
            mx0 = fmaxf(mx0, __shfl_xor_sync(0xffffffffu, mx0, 2));
            mx1 = fmaxf(mx1, __shfl_xor_sync(0xffffffffu, mx1, 1));
            mx1 = fmaxf(mx1, __shfl_xor_sync(0xffffffffu, mx1, 2));
            if (lr == 0) {
                smax[warpC * 64 + r_loc]     = mx0;
                smax[warpC * 64 + r_loc + 8] = mx1;
            }
            __syncthreads();   // smax visible; all K reads complete

            // stage V tile (128 e-rows x 32 words from transposed layout)
            #pragma unroll
            for (int i = 0; i < 4; i++) {
                int idx = tid + i * 256;
                int row = idx >> 3, cw = (idx & 7) * 4;
                cp_async16(Vs + row * 36 + cw, Vtg + (size_t)row * SEQ + k0t + cw * 2);
            }
            CP_COMMIT();

            mx0 = fmaxf(mx0, smax[(warpC ^ 1) * 64 + r_loc]);
            mx1 = fmaxf(mx1, smax[(warpC ^ 1) * 64 + r_loc + 8]);

            float mn0 = fmaxf(m0v, mx0), mn1 = fmaxf(m1v, mx1);
            float ef0 = __expf(m0v - mn0), ef1 = __expf(m1v - mn1);
            m0v = mn0; m1v = mn1;

            float sum0 = 0.f, sum1 = 0.f;
            #pragma unroll
            for (int ni = 0; ni < 4; ni++) {
                float p0 = __expf(s[ni][0] - mn0);
                float p1 = __expf(s[ni][1] - mn0);
                float p2 = __expf(s[ni][2] - mn1);
                float p3 = __expf(s[ni][3] - mn1);
                sum0 += p0 + p1; sum1 += p2 + p3;
                int kw2 = warpC * 16 + ni * 4 + lr;     // (kc2 >> 1)
                Ps[r_loc * 36 + kw2]       = ph2(p0, p1);
                Ps[(r_loc + 8) * 36 + kw2] = ph2(p2, p3);
            }
            sum0 += __shfl_xor_sync(0xffffffffu, sum0, 1);
            sum0 += __shfl_xor_sync(0xffffffffu, sum0, 2);
            sum1 += __shfl_xor_sync(0xffffffffu, sum1, 1);
            sum1 += __shfl_xor_sync(0xffffffffu, sum1, 2);
            if (lr == 0) {
                ssum[warpC * 64 + r_loc]     = sum0;
                ssum[warpC * 64 + r_loc + 8] = sum1;
            }
            #pragma unroll
            for (int ni = 0; ni < 8; ni++) {
                o[ni][0] *= ef0; o[ni][1] *= ef0;
                o[ni][2] *= ef1; o[ni][3] *= ef1;
            }

            CP_WAIT0();
            __syncthreads();   // V + Ps + ssum visible

            l0 = l0 * ef0 + sum0 + ssum[(warpC ^ 1) * 64 + r_loc];
            l1 = l1 * ef1 + sum1 + ssum[(warpC ^ 1) * 64 + r_loc + 8];

            // O += P @ V : warp 16x64, k=64 -> 4 k16 steps
            #pragma unroll
            for (int kt = 0; kt < 4; kt++) {
                unsigned ap[4], bb[2];
                const int kw = kt * 8 + lr;
                ap[0] = Ps[r_loc * 36 + kw];        ap[1] = Ps[(r_loc + 8) * 36 + kw];
                ap[2] = Ps[r_loc * 36 + kw + 4];    ap[3] = Ps[(r_loc + 8) * 36 + kw + 4];
                #pragma unroll
                for (int ni = 0; ni < 8; ni++) {
                    int nb = warpC * 64 + ni * 8 + lq;
                    bb[0] = Vs[nb * 36 + kw];
                    bb[1] = Vs[nb * 36 + kw + 4];
                    mma_f16(o[ni], ap, bb);
                }
            }
        }

        // normalize + scatter-write Z into fp16 A-frag panels
        float inv0 = 1.f / l0, inv1 = 1.f / l1;
        const int mglob0 = b * SEQ + q0;
        unsigned* Zt = g_Zp + (size_t)(mglob0 >> 7) * PANEL_W;
        const int mrow = (mglob0 & 127) + r_loc;
        #pragma unroll
        for (int ni = 0; ni < 8; ni++) {
            int e = warpC * 64 + ni * 8 + 2 * lr;
            int kg = h * DHEAD + e;
            unsigned* Zs = Zt + (size_t)(kg >> 6) * SLAB_W;
            int kl = kg & 63;
            Zs[afrag16(mrow,     kl)] = ph2(o[ni][0] * inv0, o[ni][1] * inv0);
            Zs[afrag16(mrow + 8, kl)] = ph2(o[ni][2] * inv1, o[ni][3] * inv1);
        }
    }
}

// ---------------------------------------------------------------------------
// Phase 3: output projection. grid = (16 n-tiles, 32 m-tiles)
// ---------------------------------------------------------------------------
__global__ __launch_bounds__(256) void out_gemm16(
    const float* __restrict__ bO, float* __restrict__ out)
{
    extern __shared__ __align__(16) unsigned smp[];

    const int n0  = blockIdx.x * 128;
    const int m0  = blockIdx.y * 128;
    const int tid = threadIdx.x;
    const int warp = tid >> 5, lane = tid & 31;
    const int warpM = warp >> 2, warpN = warp & 3;
    const int lq = lane >> 2, lr = lane & 3;

    const unsigned* Ablk0 = g_Zp + (size_t)(m0 >> 7) * PANEL_W;
    const unsigned* Bblk0 = g_WOp + (size_t)(n0 >> 7) * PANEL_W;

    float c[4][4][4];
    #pragma unroll
    for (int mi = 0; mi < 4; mi++)
        #pragma unroll
        for (int ni = 0; ni < 4; ni++)
            #pragma unroll
            for (int j = 0; j < 4; j++) c[mi][ni][j] = 0.f;

    gemm_issue16(smp,              Ablk0,            Bblk0,            tid); CP_COMMIT();
    gemm_issue16(smp + GSTAGE_W,   Ablk0 + SLAB_W,   Bblk0 + SLAB_W,   tid); CP_COMMIT();
    gemm_issue16(smp + 2*GSTAGE_W, Ablk0 + 2*SLAB_W, Bblk0 + 2*SLAB_W, tid); CP_COMMIT();

    int st = 0;
    for (int s = 0; s < 32; s++) {
        unsigned* cur = smp + st * GSTAGE_W;
        CP_WAIT2();
        __syncthreads();
        gemm_compute16(cur, c, warpM, warpN, lane);
        __syncthreads();
        if (s + 3 < 32)
            gemm_issue16(cur, Ablk0 + (size_t)(s + 3) * SLAB_W,
                              Bblk0 + (size_t)(s + 3) * SLAB_W, tid);
        CP_COMMIT();
        st = (st == 2) ? 0 : st + 1;
    }

    #pragma unroll
    for (int mi = 0; mi < 4; mi++) {
        #pragma unroll
        for (int half_ = 0; half_ < 2; half_++) {
            int m = m0 + warpM * 64 + mi * 16 + lq + half_ * 8;
            float* orow = out + (size_t)m * DMODEL + n0;
            #pragma unroll
            for (int ni = 0; ni < 4; ni++) {
                int n = warpN * 32 + ni * 8 + 2 * lr;
                float2 r;
                r.x = c[mi][ni][half_ * 2 + 0] + bO[n0 + n];
                r.y = c[mi][ni][half_ * 2 + 1] + bO[n0 + n + 1];
                *(float2*)(orow + n) = r;
            }
        }
    }
}

// ---------------------------------------------------------------------------
extern "C" void kernel_launch(void* const* d_in, const int* in_sizes, int n_in,
                              void* d_out, int out_size)
{
    const float* x  = (const float*)d_in[0];
    const float* Wq = (const float*)d_in[1];
    const float* Wk = (const float*)d_in[2];
    const float* Wv = (const float*)d_in[3];
    const float* Wo = (const float*)d_in[4];
    const float* bq = (const float*)d_in[5];
    const float* bk = (const float*)d_in[6];
    const float* bv = (const float*)d_in[7];
    const float* bo = (const float*)d_in[8];
    float* out = (float*)d_out;

    unsigned *pXp, *pWqp, *pWkp, *pWvp, *pWOp;
    cudaGetSymbolAddress((void**)&pXp,  g_Xp);
    cudaGetSymbolAddress((void**)&pWqp, g_Wqp);
    cudaGetSymbolAddress((void**)&pWkp, g_Wkp);
    cudaGetSymbolAddress((void**)&pWvp, g_Wvp);
    cudaGetSymbolAddress((void**)&pWOp, g_WOp);

    const int NXC = 32 * 32 * 1024;        // A chunks (32 m-tiles x 32 slabs x 1024)
    const int NWC = 16 * 32 * 1024;        // B chunks per weight (16 panels)
    permute_A16<<<(NXC + 255) / 256, 256>>>(x, pXp, NXC);
    permute_B16<<<(NWC + 255) / 256, 256>>>(Wq, pWqp, (size_t)DMODEL * DHEAD, DHEAD, SCALE, NWC);
    permute_B16<<<(NWC + 255) / 256, 256>>>(Wk, pWkp, (size_t)DMODEL * DHEAD, DHEAD, 1.f, NWC);
    permute_B16<<<(NWC + 255) / 256, 256>>>(Wv, pWvp, (size_t)DMODEL * DHEAD, DHEAD, 1.f, NWC);
    permute_B16<<<(NWC + 255) / 256, 256>>>(Wo, pWOp, (size_t)128, DMODEL, 1.f, NWC);

    dim3 blk(256);

    cudaFuncSetAttribute(qkv_gemm16, cudaFuncAttributeMaxDynamicSharedMemorySize, GEMM_SMEM_BYTES);
    qkv_gemm16<<<dim3(16, 32, 3), blk, GEMM_SMEM_BYTES>>>(bq, bk, bv);

    cudaFuncSetAttribute(attn16, cudaFuncAttributeMaxDynamicSharedMemorySize, ATT_SMEM_BYTES);
    attn16<<<dim3(16, 32), blk, ATT_SMEM_BYTES>>>();

    cudaFuncSetAttribute(out_gemm16, cudaFuncAttributeMaxDynamicSharedMemorySize, GEMM_SMEM_BYTES);
    out_gemm16<<<dim3(16, 32), blk, GEMM_SMEM_BYTES>>>(bo, out);
}

// round 13
// speedup vs baseline: 1.9841x; 1.0481x over previous
#include <cuda_runtime.h>
#include <cuda_fp16.h>
#include <math.h>

#define BATCH   2
#define SEQ     2048
#define DMODEL  2048
#define NHEADS  16
#define DHEAD   128
#define SCALE   0.08838834764831845f   // 1/sqrt(128)

// ---------------------------------------------------------------------------
// Scratch (allocation-free: __device__ globals)
// ---------------------------------------------------------------------------
__device__ __half g_Q [BATCH*NHEADS*SEQ*DHEAD];   // [b][h][s][e] fp16, Q pre-scaled
__device__ __half g_K [BATCH*NHEADS*SEQ*DHEAD];   // [b][h][s][e]
__device__ __half g_Vt[BATCH*NHEADS*DHEAD*SEQ];   // [b][h][e][s]  (transposed!)

// fp16 fragment-permuted operand panels (1 word = 2 fp16 along k).
#define SLAB_W  4096
#define PANEL_W (32*SLAB_W)   // 131072 words
__device__ unsigned g_Xp [BATCH*SEQ*DMODEL/2];
__device__ unsigned g_Zp [BATCH*SEQ*DMODEL/2];
__device__ unsigned g_Wqp[NHEADS*DMODEL*DHEAD/2];
__device__ unsigned g_Wkp[NHEADS*DMODEL*DHEAD/2];
__device__ unsigned g_Wvp[NHEADS*DMODEL*DHEAD/2];
__device__ unsigned g_WOp[DMODEL*DMODEL/2];

// ---------------------------------------------------------------------------
// helpers
// ---------------------------------------------------------------------------
__device__ __forceinline__ unsigned ph2(float a, float b) {
    __half2 h = __floats2half2_rn(a, b);
    return *(unsigned*)&h;
}

__device__ __forceinline__ void mma_f16(float* c, const unsigned* a, const unsigned* b) {
    asm volatile(
        "mma.sync.aligned.m16n8k16.row.col.f32.f16.f16.f32 "
        "{%0,%1,%2,%3}, {%4,%5,%6,%7}, {%8,%9}, {%0,%1,%2,%3};\n"
        : "+f"(c[0]), "+f"(c[1]), "+f"(c[2]), "+f"(c[3])
        : "r"(a[0]), "r"(a[1]), "r"(a[2]), "r"(a[3]), "r"(b[0]), "r"(b[1]));
}

__device__ __forceinline__ void cp_async16(void* smem_dst, const void* gsrc) {
    unsigned saddr = (unsigned)__cvta_generic_to_shared(smem_dst);
    asm volatile("cp.async.ca.shared.global [%0], [%1], 16;\n" :: "r"(saddr), "l"(gsrc));
}
#define CP_COMMIT() asm volatile("cp.async.commit_group;\n" ::: "memory")
#define CP_WAIT0()  asm volatile("cp.async.wait_group 0;\n" ::: "memory")
#define CP_WAIT2()  asm volatile("cp.async.wait_group 2;\n" ::: "memory")

// A-frag word index within a 128x64 fp16 slab (k even, 0..63)
__device__ __forceinline__ int afrag16(int m, int k) {
    int reg = ((k & 8) >> 2) | ((m & 8) >> 3);
    return ((((m >> 4) * 4 + (k >> 4)) * 32 + (m & 7) * 4 + ((k & 7) >> 1)) << 2) + reg;
}

// ---------------------------------------------------------------------------
// Prepass: A operand (row-major fp32 [4096][2048]) -> fp16 A-frag panels
// ---------------------------------------------------------------------------
__global__ __launch_bounds__(256) void permute_A16(
    const float* __restrict__ src, unsigned* __restrict__ dst, int nchunks)
{
    int gid = blockIdx.x * blockDim.x + threadIdx.x;
    if (gid >= nchunks) return;
    int c = gid & 1023, slab = (gid >> 10) & 31, mt_g = gid >> 15;
    int lane = c & 31, t = c >> 5;
    int kt = t & 3, mt = t >> 2;
    int m = mt_g * 128 + mt * 16 + (lane >> 2);
    int k = slab * 64 + kt * 16 + 2 * (lane & 3);
    const float* s = src + (size_t)m * DMODEL + k;
    uint4 o;
    o.x = ph2(s[0], s[1]);
    o.y = ph2(s[(size_t)8 * DMODEL], s[(size_t)8 * DMODEL + 1]);
    o.z = ph2(s[8], s[9]);
    o.w = ph2(s[(size_t)8 * DMODEL + 8], s[(size_t)8 * DMODEL + 9]);
    *(uint4*)(dst + (size_t)gid * 4) = o;
}

// ---------------------------------------------------------------------------
// Prepass: B operand -> fp16 B-frag panels.
// ---------------------------------------------------------------------------
__global__ __launch_bounds__(256) void permute_B16(
    const float* __restrict__ src, unsigned* __restrict__ dst,
    size_t mat_stride, int ld, float scl, int nchunks)
{
    int gid = blockIdx.x * blockDim.x + threadIdx.x;
    if (gid >= nchunks) return;
    int c = gid & 1023, slab = (gid >> 10) & 31, mat = gid >> 15;
    int p = c * 2;
    int L = p & 31, t = p >> 5;
    int nt = t & 15, kt = t >> 4;
    int n = nt * 8 + (L >> 2);
    int k = slab * 64 + kt * 16 + 2 * (L & 3);
    const float* s = src + (size_t)mat * mat_stride + n;
    uint4 o;
    o.x = ph2(s[(size_t)k * ld] * scl,        s[(size_t)(k + 1) * ld] * scl);
    o.y = ph2(s[(size_t)(k + 8) * ld] * scl,  s[(size_t)(k + 9) * ld] * scl);
    o.z = ph2(s[(size_t)(k + 2) * ld] * scl,  s[(size_t)(k + 3) * ld] * scl);
    o.w = ph2(s[(size_t)(k + 10) * ld] * scl, s[(size_t)(k + 11) * ld] * scl);
    *(uint4*)(dst + (size_t)gid * 4) = o;
}

// ---------------------------------------------------------------------------
// fp16 GEMM mainloop: block tile 128x128, k-slab 64, 3-stage cp.async.
// ---------------------------------------------------------------------------
#define GSTAGE_W (2 * SLAB_W)
#define GEMM_SMEM_BYTES (3 * GSTAGE_W * 4)    // 98304

__device__ __forceinline__ void gemm_issue16(
    unsigned* stage, const unsigned* __restrict__ A, const unsigned* __restrict__ B, int tid)
{
    #pragma unroll
    for (int i = 0; i < 4; i++) {
        int c = tid + i * 256;
        cp_async16(stage + c * 4, A + (size_t)c * 4);
        cp_async16(stage + SLAB_W + c * 4, B + (size_t)c * 4);
    }
}

__device__ __forceinline__ void gemm_compute16(
    const unsigned* stage, float c[4][4][4], int warpM, int warpN, int lane)
{
    const uint4* A4 = (const uint4*)stage;
    const uint2* B2 = (const uint2*)(stage + SLAB_W);
    #pragma unroll
    for (int kt = 0; kt < 4; kt++) {
        uint4 a[4]; uint2 b[4];
        #pragma unroll
        for (int mi = 0; mi < 4; mi++)
            a[mi] = A4[((warpM * 4 + mi) * 4 + kt) * 32 + lane];
        #pragma unroll
        for (int ni = 0; ni < 4; ni++)
            b[ni] = B2[(kt * 16 + warpN * 4 + ni) * 32 + lane];
        #pragma unroll
        for (int mi = 0; mi < 4; mi++)
            #pragma unroll
            for (int ni = 0; ni < 4; ni++)
                mma_f16(c[mi][ni], (const unsigned*)&a[mi], (const unsigned*)&b[ni]);
    }
}

// ---------------------------------------------------------------------------
// Phase 1: QKV projection. grid = (16 heads, 32 m-tiles, 3 {Q,K,V}).
// ---------------------------------------------------------------------------
__global__ __launch_bounds__(256) void qkv_gemm16(
    const float* __restrict__ bq, const float* __restrict__ bk, const float* __restrict__ bv)
{
    extern __shared__ __align__(16) unsigned smp[];

    const unsigned* W; const float* bias; float bscale;
    if (blockIdx.z == 0)      { W = g_Wqp; bias = bq; bscale = SCALE; }
    else if (blockIdx.z == 1) { W = g_Wkp; bias = bk; bscale = 1.f; }
    else                      { W = g_Wvp; bias = bv; bscale = 1.f; }

    const int h   = blockIdx.x;
    const int m0  = blockIdx.y * 128;
    const int tid = threadIdx.x;
    const int warp = tid >> 5, lane = tid & 31;
    const int warpM = warp >> 2, warpN = warp & 3;
    const int lq = lane >> 2, lr = lane & 3;
    const unsigned* Ablk0 = g_Xp + (size_t)(m0 >> 7) * PANEL_W;
    const unsigned* Bblk0 = W + (size_t)h * PANEL_W;

    float c[4][4][4];
    #pragma unroll
    for (int mi = 0; mi < 4; mi++)
        #pragma unroll
        for (int ni = 0; ni < 4; ni++)
            #pragma unroll
            for (int j = 0; j < 4; j++) c[mi][ni][j] = 0.f;

    gemm_issue16(smp,              Ablk0,              Bblk0,              tid); CP_COMMIT();
    gemm_issue16(smp + GSTAGE_W,   Ablk0 + SLAB_W,     Bblk0 + SLAB_W,     tid); CP_COMMIT();
    gemm_issue16(smp + 2*GSTAGE_W, Ablk0 + 2*SLAB_W,   Bblk0 + 2*SLAB_W,   tid); CP_COMMIT();

    int st = 0;
    for (int s = 0; s < 32; s++) {
        unsigned* cur = smp + st * GSTAGE_W;
        CP_WAIT2();
        __syncthreads();
        gemm_compute16(cur, c, warpM, warpN, lane);
        __syncthreads();
        if (s + 3 < 32)
            gemm_issue16(cur, Ablk0 + (size_t)(s + 3) * SLAB_W,
                              Bblk0 + (size_t)(s + 3) * SLAB_W, tid);
        CP_COMMIT();
        st = (st == 2) ? 0 : st + 1;
    }

    #pragma unroll
    for (int mi = 0; mi < 4; mi++) {
        #pragma unroll
        for (int half_ = 0; half_ < 2; half_++) {
            int m = m0 + warpM * 64 + mi * 16 + lq + half_ * 8;
            int b_ = m >> 11, sdx = m & 2047;
            const size_t head = (size_t)(b_ * NHEADS + h);
            #pragma unroll
            for (int ni = 0; ni < 4; ni++) {
                int n = warpN * 32 + ni * 8 + 2 * lr;
                float v0 = c[mi][ni][half_ * 2 + 0] + bias[h * DHEAD + n]     * bscale;
                float v1 = c[mi][ni][half_ * 2 + 1] + bias[h * DHEAD + n + 1] * bscale;
                if (blockIdx.z == 2) {
                    __half* vt = g_Vt + head * DHEAD * SEQ;
                    vt[(size_t)n * SEQ + sdx]       = __float2half_rn(v0);
                    vt[(size_t)(n + 1) * SEQ + sdx] = __float2half_rn(v1);
                } else {
                    __half* orow = (blockIdx.z == 0 ? g_Q : g_K)
                                   + (head * SEQ + sdx) * DHEAD;
                    *(unsigned*)(orow + n) = ph2(v0, v1);
                }
            }
        }
    }
}

// ---------------------------------------------------------------------------
// Phase 2: causal flash attention, register-resident P.
// q-tile 128, kv-tile 64, 256 threads = 8 warps; each warp owns 16 q-rows and
// the FULL 64-key width -> softmax is warp-local (quad shfl), P stays in regs
// (S c-frag == PV a-frag layout). 2 barriers per kv-tile.
// grid = (8 pair-slots, B*H); CTA runs q-tiles {15-i, i} (34 kv-tiles each).
// ---------------------------------------------------------------------------
#define AQ  0
#define AK  (128*68)           // 8704
#define AV  (AK + 64*68)       // 13056
#define ATT_SMEM_W (AV + 128*36)   // 17664 words
#define ATT_SMEM_BYTES (ATT_SMEM_W * 4)   // 70656

__global__ __launch_bounds__(256, 2) void attn16()
{
    extern __shared__ __align__(16) unsigned smu[];
    unsigned* Qs = smu + AQ;   // [128][68] words (64 used/row)
    unsigned* Ks = smu + AK;   // [64][68]
    unsigned* Vs = smu + AV;   // [128][36] (32 used/row), rows = e, words = key pairs

    const int tid = threadIdx.x;
    const int warp = tid >> 5, lane = tid & 31;
    const int lq = lane >> 2, lr = lane & 3;
    const int bh = blockIdx.y;
    const int b  = bh >> 4, h = bh & 15;
    const int r_loc = warp * 16 + lq;    // 0..127

    const __half* Qg  = g_Q  + (size_t)(b * NHEADS + h) * SEQ * DHEAD;
    const __half* Kg  = g_K  + (size_t)(b * NHEADS + h) * SEQ * DHEAD;
    const __half* Vtg = g_Vt + (size_t)(b * NHEADS + h) * DHEAD * SEQ;

    for (int run = 0; run < 2; run++) {
        const int qt = (run == 0) ? (15 - (int)blockIdx.x) : (int)blockIdx.x;
        const int q0 = qt * 128;
        const int ntiles = 2 * qt + 2;

        // stage Q (128 rows x 64 words)
        #pragma unroll
        for (int i = 0; i < 8; i++) {
            int idx = tid + i * 256;
            int row = idx >> 4, cw = (idx & 15) * 4;
            cp_async16(Qs + row * 68 + cw, Qg + (size_t)(q0 + row) * DHEAD + cw * 2);
        }
        CP_COMMIT();

        float o[16][4];
        #pragma unroll
        for (int ni = 0; ni < 16; ni++)
            #pragma unroll
            for (int j = 0; j < 4; j++) o[ni][j] = 0.f;
        float m0v = -INFINITY, m1v = -INFINITY, l0 = 0.f, l1 = 0.f;

        for (int kt2 = 0; kt2 < ntiles; kt2++) {
            const int k0t = kt2 * 64;
            // stage K tile (64 rows x 64 words) + V tile (128 rows x 32 words)
            #pragma unroll
            for (int i = 0; i < 4; i++) {
                int idx = tid + i * 256;
                int row = idx >> 4, cw = (idx & 15) * 4;
                cp_async16(Ks + row * 68 + cw, Kg + (size_t)(k0t + row) * DHEAD + cw * 2);
            }
            #pragma unroll
            for (int i = 0; i < 4; i++) {
                int idx = tid + i * 256;
                int row = idx >> 3, cw = (idx & 7) * 4;
                cp_async16(Vs + row * 36 + cw, Vtg + (size_t)row * SEQ + k0t + cw * 2);
            }
            CP_COMMIT();
            CP_WAIT0();
            __syncthreads();   // K, V (and Q on first tile) visible

            // S = Q K^T : warp 16 x 64 (8 n-tiles), k=128 -> 8 k16 steps
            float s[8][4];
            #pragma unroll
            for (int ni = 0; ni < 8; ni++)
                #pragma unroll
                for (int j = 0; j < 4; j++) s[ni][j] = 0.f;

            #pragma unroll
            for (int kt = 0; kt < 8; kt++) {
                unsigned aq[4];
                const int kw = kt * 8 + lr;
                aq[0] = Qs[r_loc * 68 + kw];        aq[1] = Qs[(r_loc + 8) * 68 + kw];
                aq[2] = Qs[r_loc * 68 + kw + 4];    aq[3] = Qs[(r_loc + 8) * 68 + kw + 4];
                #pragma unroll
                for (int ni = 0; ni < 8; ni++) {
                    unsigned bb[2];
                    int nb = ni * 8 + lq;
                    bb[0] = Ks[nb * 68 + kw];
                    bb[1] = Ks[nb * 68 + kw + 4];
                    mma_f16(s[ni], aq, bb);
                }
            }

            // causal mask + warp-local row max (quad shuffle)
            const int r0g = q0 + r_loc, r1g = r0g + 8;
            float mx0 = -1e30f, mx1 = -1e30f;
            #pragma unroll
            for (int ni = 0; ni < 8; ni++) {
                int cb = k0t + ni * 8 + 2 * lr;
                if (cb     > r0g) s[ni][0] = -1e30f;
                if (cb + 1 > r0g) s[ni][1] = -1e30f;
                if (cb     > r1g) s[ni][2] = -1e30f;
                if (cb + 1 > r1g) s[ni][3] = -1e30f;
                mx0 = fmaxf(mx0, fmaxf(s[ni][0], s[ni][1]));
                mx1 = fmaxf(mx1, fmaxf(s[ni][2], s[ni][3]));
            }
            mx0 = fmaxf(mx0, __shfl_xor_sync(0xffffffffu, mx0, 1));
            mx0 = fmaxf(mx0, __shfl_xor_sync(0xffffffffu, mx0, 2));
            mx1 = fmaxf(mx1, __shfl_xor_sync(0xffffffffu, mx1, 1));
            mx1 = fmaxf(mx1, __shfl_xor_sync(0xffffffffu, mx1, 2));

            float mn0 = fmaxf(m0v, mx0), mn1 = fmaxf(m1v, mx1);
            float ef0 = __expf(m0v - mn0), ef1 = __expf(m1v - mn1);
            m0v = mn0; m1v = mn1;

            // exp + row sum + pack P to fp16 a-frag words (register-resident)
            float sum0 = 0.f, sum1 = 0.f;
            unsigned p01[8], p23[8];
            #pragma unroll
            for (int ni = 0; ni < 8; ni++) {
                float e0 = __expf(s[ni][0] - mn0);
                float e1 = __expf(s[ni][1] - mn0);
                float e2 = __expf(s[ni][2] - mn1);
                float e3 = __expf(s[ni][3] - mn1);
                sum0 += e0 + e1; sum1 += e2 + e3;
                p01[ni] = ph2(e0, e1);
                p23[ni] = ph2(e2, e3);
            }
            sum0 += __shfl_xor_sync(0xffffffffu, sum0, 1);
            sum0 += __shfl_xor_sync(0xffffffffu, sum0, 2);
            sum1 += __shfl_xor_sync(0xffffffffu, sum1, 1);
            sum1 += __shfl_xor_sync(0xffffffffu, sum1, 2);
            l0 = l0 * ef0 + sum0;
            l1 = l1 * ef1 + sum1;

            // rescale O
            #pragma unroll
            for (int ni = 0; ni < 16; ni++) {
                o[ni][0] *= ef0; o[ni][1] *= ef0;
                o[ni][2] *= ef1; o[ni][3] *= ef1;
            }

            // O += P @ V : warp 16 x 128 (16 n-tiles), k=64 -> 4 k16 steps
            #pragma unroll
            for (int t = 0; t < 4; t++) {
                unsigned ap[4] = { p01[2*t], p23[2*t], p01[2*t + 1], p23[2*t + 1] };
                const int kw = t * 8 + lr;
                #pragma unroll
                for (int ni = 0; ni < 16; ni++) {
                    unsigned bb[2];
                    int nb = ni * 8 + lq;
                    bb[0] = Vs[nb * 36 + kw];
                    bb[1] = Vs[nb * 36 + kw + 4];
                    mma_f16(o[ni], ap, bb);
                }
            }
            __syncthreads();   // all warps done with Ks/Vs before restaging
        }

        // normalize + scatter-write Z into fp16 A-frag panels
        float inv0 = 1.f / l0, inv1 = 1.f / l1;
        const int mglob0 = b * SEQ + q0;     // 128-aligned
        unsigned* Zt = g_Zp + (size_t)(mglob0 >> 7) * PANEL_W;
        const int mrow = r_loc;
        #pragma unroll
        for (int ni = 0; ni < 16; ni++) {
            int e = ni * 8 + 2 * lr;
            int kg = h * DHEAD + e;
            unsigned* Zs = Zt + (size_t)(kg >> 6) * SLAB_W;
            int kl = kg & 63;
            Zs[afrag16(mrow,     kl)] = ph2(o[ni][0] * inv0, o[ni][1] * inv0);
            Zs[afrag16(mrow + 8, kl)] = ph2(o[ni][2] * inv1, o[ni][3] * inv1);
        }
    }
}

// ---------------------------------------------------------------------------
// Phase 3: output projection. grid = (16 n-tiles, 32 m-tiles)
// ---------------------------------------------------------------------------
__global__ __launch_bounds__(256) void out_gemm16(
    const float* __restrict__ bO, float* __restrict__ out)
{
    extern __shared__ __align__(16) unsigned smp[];

    const int n0  = blockIdx.x * 128;
    const int m0  = blockIdx.y * 128;
    const int tid = threadIdx.x;
    const int warp = tid >> 5, lane = tid & 31;
    const int warpM = warp >> 2, warpN = warp & 3;
    const int lq = lane >> 2, lr = lane & 3;

    const unsigned* Ablk0 = g_Zp + (size_t)(m0 >> 7) * PANEL_W;
    const unsigned* Bblk0 = g_WOp + (size_t)(n0 >> 7) * PANEL_W;

    float c[4][4][4];
    #pragma unroll
    for (int mi = 0; mi < 4; mi++)
        #pragma unroll
        for (int ni = 0; ni < 4; ni++)
            #pragma unroll
            for (int j = 0; j < 4; j++) c[mi][ni][j] = 0.f;

    gemm_issue16(smp,              Ablk0,            Bblk0,            tid); CP_COMMIT();
    gemm_issue16(smp + GSTAGE_W,   Ablk0 + SLAB_W,   Bblk0 + SLAB_W,   tid); CP_COMMIT();
    gemm_issue16(smp + 2*GSTAGE_W, Ablk0 + 2*SLAB_W, Bblk0 + 2*SLAB_W, tid); CP_COMMIT();

    int st = 0;
    for (int s = 0; s < 32; s++) {
        unsigned* cur = smp + st * GSTAGE_W;
        CP_WAIT2();
        __syncthreads();
        gemm_compute16(cur, c, warpM, warpN, lane);
        __syncthreads();
        if (s + 3 < 32)
            gemm_issue16(cur, Ablk0 + (size_t)(s + 3) * SLAB_W,
                              Bblk0 + (size_t)(s + 3) * SLAB_W, tid);
        CP_COMMIT();
        st = (st == 2) ? 0 : st + 1;
    }

    #pragma unroll
    for (int mi = 0; mi < 4; mi++) {
        #pragma unroll
        for (int half_ = 0; half_ < 2; half_++) {
            int m = m0 + warpM * 64 + mi * 16 + lq + half_ * 8;
            float* orow = out + (size_t)m * DMODEL + n0;
            #pragma unroll
            for (int ni = 0; ni < 4; ni++) {
                int n = warpN * 32 + ni * 8 + 2 * lr;
                float2 r;
                r.x = c[mi][ni][half_ * 2 + 0] + bO[n0 + n];
                r.y = c[mi][ni][half_ * 2 + 1] + bO[n0 + n + 1];
                *(float2*)(orow + n) = r;
            }
        }
    }
}

// ---------------------------------------------------------------------------
extern "C" void kernel_launch(void* const* d_in, const int* in_sizes, int n_in,
                              void* d_out, int out_size)
{
    const float* x  = (const float*)d_in[0];
    const float* Wq = (const float*)d_in[1];
    const float* Wk = (const float*)d_in[2];
    const float* Wv = (const float*)d_in[3];
    const float* Wo = (const float*)d_in[4];
    const float* bq = (const float*)d_in[5];
    const float* bk = (const float*)d_in[6];
    const float* bv = (const float*)d_in[7];
    const float* bo = (const float*)d_in[8];
    float* out = (float*)d_out;

    unsigned *pXp, *pWqp, *pWkp, *pWvp, *pWOp;
    cudaGetSymbolAddress((void**)&pXp,  g_Xp);
    cudaGetSymbolAddress((void**)&pWqp, g_Wqp);
    cudaGetSymbolAddress((void**)&pWkp, g_Wkp);
    cudaGetSymbolAddress((void**)&pWvp, g_Wvp);
    cudaGetSymbolAddress((void**)&pWOp, g_WOp);

    const int NXC = 32 * 32 * 1024;
    const int NWC = 16 * 32 * 1024;
    permute_A16<<<(NXC + 255) / 256, 256>>>(x, pXp, NXC);
    permute_B16<<<(NWC + 255) / 256, 256>>>(Wq, pWqp, (size_t)DMODEL * DHEAD, DHEAD, SCALE, NWC);
    permute_B16<<<(NWC + 255) / 256, 256>>>(Wk, pWkp, (size_t)DMODEL * DHEAD, DHEAD, 1.f, NWC);
    permute_B16<<<(NWC + 255) / 256, 256>>>(Wv, pWvp, (size_t)DMODEL * DHEAD, DHEAD, 1.f, NWC);
    permute_B16<<<(NWC + 255) / 256, 256>>>(Wo, pWOp, (size_t)128, DMODEL, 1.f, NWC);

    dim3 blk(256);

    cudaFuncSetAttribute(qkv_gemm16, cudaFuncAttributeMaxDynamicSharedMemorySize, GEMM_SMEM_BYTES);
    qkv_gemm16<<<dim3(16, 32, 3), blk, GEMM_SMEM_BYTES>>>(bq, bk, bv);

    cudaFuncSetAttribute(attn16, cudaFuncAttributeMaxDynamicSharedMemorySize, ATT_SMEM_BYTES);
    attn16<<<dim3(8, 32), blk, ATT_SMEM_BYTES>>>();

    cudaFuncSetAttribute(out_gemm16, cudaFuncAttributeMaxDynamicSharedMemorySize, GEMM_SMEM_BYTES);
    out_gemm16<<<dim3(16, 32), blk, GEMM_SMEM_BYTES>>>(bo, out);
}